// round 12
// baseline (speedup 1.0000x reference)
#include <cuda_runtime.h>
#include <cuda_fp16.h>
#include <math.h>
#include <stdint.h>

#define DDIM 256
#define NMAX 100000
#define MMAX 50000

// ---------------- device scratch (static; no runtime allocs) ---------------
__device__ __half g_W[3 * 256 * 256];       // transposed [n][k] fp16 (o,p,k)
__device__ __half g_L[256 * 768];           // linear_w [n][k] fp16
__device__ __half g_T[(size_t)MMAX * 768];  // tanh concat (A of final GEMM)
__device__ __half g_Ahp[(size_t)NMAX * 256];
__device__ __half g_Ahk[(size_t)NMAX * 256];
__device__ __half g_Aho[(size_t)MMAX * 256];
__device__ int    g_invP[NMAX];
__device__ int    g_invK[NMAX];

// ---------------- helpers --------------------------------------------------
__device__ __forceinline__ uint32_t smem_u32(const void* p) {
    uint32_t a;
    asm("{ .reg .u64 t; cvta.to.shared.u64 t, %1; cvt.u32.u64 %0, t; }" : "=r"(a) : "l"(p));
    return a;
}
__device__ __forceinline__ void ldmx4(uint32_t& r0, uint32_t& r1, uint32_t& r2, uint32_t& r3,
                                      uint32_t addr) {
    asm volatile("ldmatrix.sync.aligned.m8n8.x4.shared.b16 {%0,%1,%2,%3}, [%4];"
                 : "=r"(r0), "=r"(r1), "=r"(r2), "=r"(r3) : "r"(addr));
}
__device__ __forceinline__ void mma16816(float* d, uint32_t a0, uint32_t a1, uint32_t a2,
                                         uint32_t a3, uint32_t b0, uint32_t b1) {
    asm volatile(
        "mma.sync.aligned.m16n8k16.row.col.f32.f16.f16.f32 "
        "{%0,%1,%2,%3}, {%4,%5,%6,%7}, {%8,%9}, {%0,%1,%2,%3};"
        : "+f"(d[0]), "+f"(d[1]), "+f"(d[2]), "+f"(d[3])
        : "r"(a0), "r"(a1), "r"(a2), "r"(a3), "r"(b0), "r"(b1));
}
__device__ __forceinline__ void cp_async16(uint32_t dst, const void* src, bool pred) {
    int sz = pred ? 16 : 0;
    asm volatile("cp.async.cg.shared.global [%0], [%1], 16, %2;"
                 :: "r"(dst), "l"(src), "r"(sz));
}
#define CP_COMMIT()   asm volatile("cp.async.commit_group;" ::: "memory")
#define CP_WAIT_ALL() asm volatile("cp.async.wait_group 0;" ::: "memory")
#define CP_WAIT_1()   asm volatile("cp.async.wait_group 1;" ::: "memory")
#define SW128(o) ((o) ^ (((o) >> 3) & 0x70))

// ---------------------------------------------------------------------------
// gemm3 (256 threads): z=0 hp, z=1 hk (out + cond tanh->T), z=2 ho (tanh->T)
// 3-stage cp.async pipeline, BM=128, BN=128, BK=64.
// ---------------------------------------------------------------------------
#define G3_BUF 32768
#define G3_OFF_A 0
#define G3_OFF_B 16384
#define G3_SMEM (3 * G3_BUF)

struct Args3 {
    const __half* A0; const __half* A1; const __half* A2;
    const __half* B0; const __half* B1; const __half* B2;
    float* outF;
    __half* T;
    const int* invP;
    const int* invK;
    int N;
    int M;
};

__global__ void __launch_bounds__(256, 2)
gemm3(const Args3 args)
{
    extern __shared__ char smem[];
    const uint32_t sb = smem_u32(smem);
    const int tid = threadIdx.x;
    const int w = tid >> 5;
    const int lane = tid & 31;
    const int z = blockIdx.z;
    const int rowBase = blockIdx.x * 128;
    const int colBase = blockIdx.y * 128;
    const int rowsC = (z == 2) ? args.M : args.N;
    if (rowBase >= rowsC) return;

    const __half* Ah = (z == 0) ? args.A0 : ((z == 1) ? args.A1 : args.A2);
    const __half* B  = (z == 0) ? args.B0 : ((z == 1) ? args.B1 : args.B2);

    const int wm = w & 1;
    const int wn = w >> 1;

    float acc[64];
    #pragma unroll
    for (int i = 0; i < 64; i++) acc[i] = 0.0f;

    const int lr = tid >> 3;
    const int lj8 = (tid & 7) * 8;
    const uint32_t soA[4] = {
        SW128((uint32_t)((lr + 0) * 128 + lj8 * 2)),
        SW128((uint32_t)((lr + 32) * 128 + lj8 * 2)),
        SW128((uint32_t)((lr + 64) * 128 + lj8 * 2)),
        SW128((uint32_t)((lr + 96) * 128 + lj8 * 2))};

    auto issue_chunk = [&](int c) {
        const int k0 = c * 64;
        const uint32_t bufb = sb + (uint32_t)(c % 3) * G3_BUF;
        #pragma unroll
        for (int i = 0; i < 4; i++) {
            int gr = rowBase + lr + i * 32;
            bool ok = (gr < rowsC);
            const __half* src = Ah + (size_t)(ok ? gr : 0) * 256 + k0 + lj8;
            cp_async16(bufb + G3_OFF_A + soA[i], src, ok);
        }
        #pragma unroll
        for (int i = 0; i < 4; i++) {
            int n = lr + i * 32;
            size_t off = (size_t)(colBase + n) * 256 + k0 + lj8;
            cp_async16(bufb + G3_OFF_B + soA[i], B + off, true);
        }
        CP_COMMIT();
    };

    const int bnrow = wn * 32 + ((lane >> 4) & 1) * 8 + (lane & 7);
    const uint32_t bcol16 = (uint32_t)(((lane >> 3) & 1) * 16);
    const int amrow = wm * 64 + (lane & 15);
    const uint32_t acol16 = (uint32_t)((lane >> 4) * 16);

    issue_chunk(0);
    issue_chunk(1);

    for (int c = 0; c < 4; c++) {
        if (c == 3) { CP_WAIT_ALL(); } else { CP_WAIT_1(); }
        __syncthreads();
        if (c + 2 < 4) issue_chunk(c + 2);

        const uint32_t bufb = sb + (uint32_t)(c % 3) * G3_BUF;
        #pragma unroll
        for (int ks = 0; ks < 4; ks++) {
            uint32_t b[4][2];
            uint32_t a[4][4];
            #pragma unroll
            for (int np = 0; np < 2; np++) {
                uint32_t ad = bufb + G3_OFF_B +
                    SW128((uint32_t)((bnrow + np * 16) * 128) + (uint32_t)(ks * 32) + bcol16);
                ldmx4(b[np * 2][0], b[np * 2][1], b[np * 2 + 1][0], b[np * 2 + 1][1], ad);
            }
            #pragma unroll
            for (int mf = 0; mf < 4; mf++) {
                uint32_t ad = bufb + G3_OFF_A +
                    SW128((uint32_t)((amrow + mf * 16) * 128) + (uint32_t)(ks * 32) + acol16);
                ldmx4(a[mf][0], a[mf][1], a[mf][2], a[mf][3], ad);
            }
            #pragma unroll
            for (int mf = 0; mf < 4; mf++)
                #pragma unroll
                for (int nf = 0; nf < 4; nf++)
                    mma16816(&acc[mf * 16 + nf * 4],
                             a[mf][0], a[mf][1], a[mf][2], a[mf][3],
                             b[nf][0], b[nf][1]);
        }
    }

    // ---- epilogue ----
    float* outBase = (z == 1) ? (args.outF + (size_t)args.N * 256) : args.outF;
    const int* inv = (z == 0) ? args.invP : args.invK;
    const int tcolOff = (z == 0) ? 256 : ((z == 1) ? 512 : 0);

    #pragma unroll
    for (int mf = 0; mf < 4; mf++) {
        int r0 = rowBase + wm * 64 + mf * 16 + (lane >> 2);
        #pragma unroll
        for (int half = 0; half < 2; half++) {
            int r = r0 + half * 8;
            if (r >= rowsC) continue;
            int tm = (z == 2) ? r : __ldg(inv + r);
            #pragma unroll
            for (int nf = 0; nf < 4; nf++) {
                int col = colBase + wn * 32 + nf * 8 + (lane & 3) * 2;
                float v0 = acc[mf * 16 + nf * 4 + half * 2 + 0];
                float v1 = acc[mf * 16 + nf * 4 + half * 2 + 1];
                if (z != 2) {
                    *(float2*)(outBase + (size_t)r * 256 + col) = make_float2(v0, v1);
                }
                if (tm >= 0) {
                    union { __half h[2]; uint32_t u; } t;
                    t.h[0] = __float2half_rn(tanhf(v0));
                    t.h[1] = __float2half_rn(tanhf(v1));
                    *(uint32_t*)(args.T + (size_t)tm * 768 + tcolOff + col) = t.u;
                }
            }
        }
    }
}

// ---------------------------------------------------------------------------
// gemm_final (512 threads): BM=128, BN=256 (full N, grid.y=1), BK=64, K=768,
// 3-stage pipeline. +lb, leaky, +bias, scatter to out rows idxP / N+idxK.
// ---------------------------------------------------------------------------
#define GF_BUF 49152
#define GF_OFF_A 0
#define GF_OFF_B 16384
#define GF_SMEM (3 * GF_BUF)

struct ArgsF {
    const __half* Ah;
    const __half* B;
    float* outF;
    const int* idxP;
    const int* idxK;
    const float* lb;
    const float* bias;
    int rowsC;
    int Nfull;
};

__global__ void __launch_bounds__(512, 1)
gemm_final(const ArgsF args)
{
    extern __shared__ char smem[];
    const uint32_t sb = smem_u32(smem);
    const int tid = threadIdx.x;
    const int w = tid >> 5;          // 0..15
    const int lane = tid & 31;
    const int rowBase = blockIdx.x * 128;
    const int rowsC = args.rowsC;

    const int wm = w & 3;            // 4 m-subtiles of 32 rows (mf 0..1)
    const int wn = w >> 2;           // 4 n-subtiles of 64 cols (nf 0..7)

    float acc[64];                   // [mf(2)][nf(8)][4]
    #pragma unroll
    for (int i = 0; i < 64; i++) acc[i] = 0.0f;

    // loader geometry: lr 0..63, 8 threads per 64-fp16 row
    const int lr = tid >> 3;
    const int lj8 = (tid & 7) * 8;
    const uint32_t so[4] = {
        SW128((uint32_t)((lr + 0) * 128 + lj8 * 2)),
        SW128((uint32_t)((lr + 64) * 128 + lj8 * 2)),
        SW128((uint32_t)((lr + 128) * 128 + lj8 * 2)),
        SW128((uint32_t)((lr + 192) * 128 + lj8 * 2))};

    auto issue_chunk = [&](int c) {
        const int k0 = c * 64;
        const uint32_t bufb = sb + (uint32_t)(c % 3) * GF_BUF;
        // A: 128 rows (i = 0,1)
        #pragma unroll
        for (int i = 0; i < 2; i++) {
            int gr = rowBase + lr + i * 64;
            bool ok = (gr < rowsC);
            const __half* src = args.Ah + (size_t)(ok ? gr : 0) * 768 + k0 + lj8;
            cp_async16(bufb + GF_OFF_A + so[i], src, ok);
        }
        // B: 256 rows (i = 0..3)
        #pragma unroll
        for (int i = 0; i < 4; i++) {
            int n = lr + i * 64;
            size_t off = (size_t)n * 768 + k0 + lj8;
            cp_async16(bufb + GF_OFF_B + so[i], args.B + off, true);
        }
        CP_COMMIT();
    };

    const int bnrow = wn * 64 + ((lane >> 4) & 1) * 8 + (lane & 7);
    const uint32_t bcol16 = (uint32_t)(((lane >> 3) & 1) * 16);
    const int amrow = wm * 32 + (lane & 15);
    const uint32_t acol16 = (uint32_t)((lane >> 4) * 16);

    issue_chunk(0);
    issue_chunk(1);

    for (int c = 0; c < 12; c++) {
        if (c == 11) { CP_WAIT_ALL(); } else { CP_WAIT_1(); }
        __syncthreads();
        if (c + 2 < 12) issue_chunk(c + 2);

        const uint32_t bufb = sb + (uint32_t)(c % 3) * GF_BUF;
        #pragma unroll
        for (int ks = 0; ks < 4; ks++) {
            uint32_t b[8][2];
            uint32_t a[2][4];
            #pragma unroll
            for (int np = 0; np < 4; np++) {
                uint32_t ad = bufb + GF_OFF_B +
                    SW128((uint32_t)((bnrow + np * 16) * 128) + (uint32_t)(ks * 32) + bcol16);
                ldmx4(b[np * 2][0], b[np * 2][1], b[np * 2 + 1][0], b[np * 2 + 1][1], ad);
            }
            #pragma unroll
            for (int mf = 0; mf < 2; mf++) {
                uint32_t ad = bufb + GF_OFF_A +
                    SW128((uint32_t)((amrow + mf * 16) * 128) + (uint32_t)(ks * 32) + acol16);
                ldmx4(a[mf][0], a[mf][1], a[mf][2], a[mf][3], ad);
            }
            #pragma unroll
            for (int mf = 0; mf < 2; mf++)
                #pragma unroll
                for (int nf = 0; nf < 8; nf++)
                    mma16816(&acc[(mf * 8 + nf) * 4],
                             a[mf][0], a[mf][1], a[mf][2], a[mf][3],
                             b[nf][0], b[nf][1]);
        }
    }

    #pragma unroll
    for (int mf = 0; mf < 2; mf++) {
        int r0 = rowBase + wm * 32 + mf * 16 + (lane >> 2);
        #pragma unroll
        for (int half = 0; half < 2; half++) {
            int r = r0 + half * 8;
            if (r >= rowsC) continue;
            int pr = __ldg(args.idxP + r);
            int kr = __ldg(args.idxK + r);
            #pragma unroll
            for (int nf = 0; nf < 8; nf++) {
                int col = wn * 64 + nf * 8 + (lane & 3) * 2;
                float x0 = acc[(mf * 8 + nf) * 4 + half * 2 + 0] + __ldg(args.lb + col);
                float x1 = acc[(mf * 8 + nf) * 4 + half * 2 + 1] + __ldg(args.lb + col + 1);
                x0 = (x0 > 0.0f) ? x0 : 0.01f * x0;
                x1 = (x1 > 0.0f) ? x1 : 0.01f * x1;
                x0 += __ldg(args.bias + col);
                x1 += __ldg(args.bias + col + 1);
                float2 v = make_float2(x0, x1);
                *(float2*)(args.outF + (size_t)pr * 256 + col) = v;
                *(float2*)(args.outF + (size_t)(args.Nfull + kr) * 256 + col) = v;
            }
        }
    }
}

// ---------------------------------------------------------------------------
__global__ void init_inv(int* __restrict__ invP, int* __restrict__ invK, int N)
{
    int i = blockIdx.x * blockDim.x + threadIdx.x;
    if (i < N) { invP[i] = -1; invK[i] = -1; }
}

__global__ void prep_all(const float* __restrict__ wo, const float* __restrict__ wp,
                         const float* __restrict__ wk, const float* __restrict__ lw,
                         const float* __restrict__ hp, const float* __restrict__ hk,
                         const float* __restrict__ ho,
                         const int* __restrict__ idxP, const int* __restrict__ idxK,
                         __half* __restrict__ W, __half* __restrict__ L,
                         __half* __restrict__ Ahp, __half* __restrict__ Ahk,
                         __half* __restrict__ Aho,
                         int* __restrict__ invP, int* __restrict__ invK,
                         int N, int M)
{
    int idx = blockIdx.x * blockDim.x + threadIdx.x;
    const int R0 = 3 * 65536;
    const int R1 = R0 + 256 * 768;
    const int R2 = R1 + N * 32;
    const int R3 = R2 + N * 32;
    const int R4 = R3 + M * 32;
    const int R5 = R4 + M;
    const int R6 = R5 + M;
    if (idx < R0) {
        int wi = idx >> 16;
        int e = idx & 65535;
        int k = e >> 8, n = e & 255;
        const float* Wf = (wi == 0) ? wo : ((wi == 1) ? wp : wk);
        W[wi * 65536 + n * 256 + k] = __float2half_rn(Wf[k * 256 + n]);
    } else if (idx < R1) {
        int e = idx - R0;
        L[e] = __float2half_rn(lw[e]);
    } else if (idx < R4) {
        const float* src;
        __half* dst;
        int r, j8;
        if (idx < R2) {
            int e = idx - R1; r = e >> 5; j8 = (e & 31) * 8; src = hp + (size_t)r * 256 + j8; dst = Ahp;
        } else if (idx < R3) {
            int e = idx - R2; r = e >> 5; j8 = (e & 31) * 8; src = hk + (size_t)r * 256 + j8; dst = Ahk;
        } else {
            int e = idx - R3; r = e >> 5; j8 = (e & 31) * 8;
            src = ho + (size_t)__ldg(idxP + r) * 256 + j8; dst = Aho;
        }
        float4 v0 = *(const float4*)src;
        float4 v1 = *(const float4*)(src + 4);
        union { __half h[8]; uint4 u; } t;
        t.h[0] = __float2half_rn(v0.x); t.h[1] = __float2half_rn(v0.y);
        t.h[2] = __float2half_rn(v0.z); t.h[3] = __float2half_rn(v0.w);
        t.h[4] = __float2half_rn(v1.x); t.h[5] = __float2half_rn(v1.y);
        t.h[6] = __float2half_rn(v1.z); t.h[7] = __float2half_rn(v1.w);
        *(uint4*)(dst + (size_t)r * 256 + j8) = t.u;
    } else if (idx < R5) {
        int m = idx - R4;
        invP[__ldg(idxP + m)] = m;
    } else if (idx < R6) {
        int m = idx - R5;
        invK[__ldg(idxK + m)] = m;
    }
}

extern "C" void kernel_launch(void* const* d_in, const int* in_sizes, int n_in,
                              void* d_out, int out_size)
{
    const float* h_p = (const float*)d_in[0];
    const float* h_k = (const float*)d_in[1];
    const float* h_o = (const float*)d_in[2];
    const int* idxP  = (const int*)d_in[3];
    const int* idxK  = (const int*)d_in[4];
    const float* w_o = (const float*)d_in[5];
    const float* w_p = (const float*)d_in[6];
    const float* w_k = (const float*)d_in[7];
    const float* lw  = (const float*)d_in[8];
    const float* lb  = (const float*)d_in[9];
    const float* bs  = (const float*)d_in[10];
    float* out = (float*)d_out;

    const int N = in_sizes[0] / DDIM;
    const int M = in_sizes[3];

    __half *W, *L, *T, *Ahp, *Ahk, *Aho;
    int *invP, *invK;
    cudaGetSymbolAddress((void**)&W, g_W);
    cudaGetSymbolAddress((void**)&L, g_L);
    cudaGetSymbolAddress((void**)&T, g_T);
    cudaGetSymbolAddress((void**)&Ahp, g_Ahp);
    cudaGetSymbolAddress((void**)&Ahk, g_Ahk);
    cudaGetSymbolAddress((void**)&Aho, g_Aho);
    cudaGetSymbolAddress((void**)&invP, g_invP);
    cudaGetSymbolAddress((void**)&invK, g_invK);

    cudaFuncSetAttribute(gemm3, cudaFuncAttributeMaxDynamicSharedMemorySize, G3_SMEM);
    cudaFuncSetAttribute(gemm_final, cudaFuncAttributeMaxDynamicSharedMemorySize, GF_SMEM);

    // 1. init inverse maps
    init_inv<<<(N + 255) / 256, 256>>>(invP, invK, N);
    // 2. prep (weights, casts, gather-cast, inverse scatter)
    {
        int total = 3 * 65536 + 256 * 768 + N * 32 + N * 32 + M * 32 + 2 * M;
        prep_all<<<(total + 255) / 256, 256>>>(w_o, w_p, w_k, lw, h_p, h_k, h_o,
                                               idxP, idxK, W, L, Ahp, Ahk, Aho,
                                               invP, invK, N, M);
    }
    // 3. hp/hk/ho GEMMs in one launch; tanh->T fused via inverse maps
    {
        dim3 grd((N + 127) / 128, 2, 3);
        Args3 a = {};
        a.A0 = Ahp; a.A1 = Ahk; a.A2 = Aho;
        a.B0 = W + 1 * 65536; a.B1 = W + 2 * 65536; a.B2 = W + 0 * 65536;
        a.outF = out; a.T = T; a.invP = invP; a.invK = invK;
        a.N = N; a.M = M;
        gemm3<<<grd, 256, G3_SMEM>>>(a);
    }
    // 4. final linear (K=768, full N per block) + leaky + bias + scatter
    {
        dim3 grd((M + 127) / 128, 1);
        ArgsF a = {};
        a.Ah = T; a.B = L;
        a.outF = out; a.idxP = idxP; a.idxK = idxK; a.lb = lb; a.bias = bs;
        a.rowsC = M; a.Nfull = N;
        gemm_final<<<grd, 512, GF_SMEM>>>(a);
    }
}

// round 13
// speedup vs baseline: 1.0400x; 1.0400x over previous
#include <cuda_runtime.h>
#include <cuda_fp16.h>
#include <math.h>
#include <stdint.h>

#define DDIM 256
#define NMAX 100000
#define MMAX 50000

// ---------------- device scratch (static; no runtime allocs) ---------------
__device__ __half g_W[3 * 256 * 256];       // transposed [n][k] fp16 (o,p,k)
__device__ __half g_L[256 * 768];           // linear_w [n][k] fp16
__device__ __half g_T[(size_t)MMAX * 768];  // tanh concat (A of final GEMM)
__device__ __half g_Ahp[(size_t)NMAX * 256];
__device__ __half g_Ahk[(size_t)NMAX * 256];
__device__ __half g_Aho[(size_t)MMAX * 256];
__device__ int    g_invP[NMAX];
__device__ int    g_invK[NMAX];

// ---------------- helpers --------------------------------------------------
__device__ __forceinline__ uint32_t smem_u32(const void* p) {
    uint32_t a;
    asm("{ .reg .u64 t; cvta.to.shared.u64 t, %1; cvt.u32.u64 %0, t; }" : "=r"(a) : "l"(p));
    return a;
}
__device__ __forceinline__ void ldmx4(uint32_t& r0, uint32_t& r1, uint32_t& r2, uint32_t& r3,
                                      uint32_t addr) {
    asm volatile("ldmatrix.sync.aligned.m8n8.x4.shared.b16 {%0,%1,%2,%3}, [%4];"
                 : "=r"(r0), "=r"(r1), "=r"(r2), "=r"(r3) : "r"(addr));
}
__device__ __forceinline__ void mma16816(float* d, uint32_t a0, uint32_t a1, uint32_t a2,
                                         uint32_t a3, uint32_t b0, uint32_t b1) {
    asm volatile(
        "mma.sync.aligned.m16n8k16.row.col.f32.f16.f16.f32 "
        "{%0,%1,%2,%3}, {%4,%5,%6,%7}, {%8,%9}, {%0,%1,%2,%3};"
        : "+f"(d[0]), "+f"(d[1]), "+f"(d[2]), "+f"(d[3])
        : "r"(a0), "r"(a1), "r"(a2), "r"(a3), "r"(b0), "r"(b1));
}
__device__ __forceinline__ void cp_async16(uint32_t dst, const void* src, bool pred) {
    int sz = pred ? 16 : 0;
    asm volatile("cp.async.cg.shared.global [%0], [%1], 16, %2;"
                 :: "r"(dst), "l"(src), "r"(sz));
}
#define CP_COMMIT()   asm volatile("cp.async.commit_group;" ::: "memory")
#define CP_WAIT_ALL() asm volatile("cp.async.wait_group 0;" ::: "memory")
#define CP_WAIT_1()   asm volatile("cp.async.wait_group 1;" ::: "memory")
#define SW128(o) ((o) ^ (((o) >> 3) & 0x70))

// smem: 3 buffers of {A 16KB, B 16KB}
#define BUF 32768
#define OFF_A 0
#define OFF_B 16384
#define SMEM3 (3 * BUF)

// ---------------------------------------------------------------------------
// gemm3 (256 threads): z=0 hp, z=1 hk, z=2 ho. BM=128 BN=128 BK=64, 3-stage.
// Epilogue: rows with inv>=0 go tanh->T only (final scatter overwrites out);
// rows with inv<0 go to out only. z=2 always tanh->T.
// ---------------------------------------------------------------------------
struct Args3 {
    const __half* A0; const __half* A1; const __half* A2;
    const __half* B0; const __half* B1; const __half* B2;
    float* outF;
    __half* T;
    const int* invP;
    const int* invK;
    int N;
    int M;
};

__global__ void __launch_bounds__(256, 2)
gemm3(const Args3 args)
{
    extern __shared__ char smem[];
    const uint32_t sb = smem_u32(smem);
    const int tid = threadIdx.x;
    const int w = tid >> 5;
    const int lane = tid & 31;
    const int z = blockIdx.z;
    const int rowBase = blockIdx.x * 128;
    const int colBase = blockIdx.y * 128;
    const int rowsC = (z == 2) ? args.M : args.N;
    if (rowBase >= rowsC) return;

    const __half* Ah = (z == 0) ? args.A0 : ((z == 1) ? args.A1 : args.A2);
    const __half* B  = (z == 0) ? args.B0 : ((z == 1) ? args.B1 : args.B2);

    const int wm = w & 1;
    const int wn = w >> 1;

    float acc[64];
    #pragma unroll
    for (int i = 0; i < 64; i++) acc[i] = 0.0f;

    const int lr = tid >> 3;
    const int lj8 = (tid & 7) * 8;
    const uint32_t soA[4] = {
        SW128((uint32_t)((lr + 0) * 128 + lj8 * 2)),
        SW128((uint32_t)((lr + 32) * 128 + lj8 * 2)),
        SW128((uint32_t)((lr + 64) * 128 + lj8 * 2)),
        SW128((uint32_t)((lr + 96) * 128 + lj8 * 2))};

    auto issue_chunk = [&](int c) {
        const int k0 = c * 64;
        const uint32_t bufb = sb + (uint32_t)(c % 3) * BUF;
        #pragma unroll
        for (int i = 0; i < 4; i++) {
            int gr = rowBase + lr + i * 32;
            bool ok = (gr < rowsC);
            const __half* src = Ah + (size_t)(ok ? gr : 0) * 256 + k0 + lj8;
            cp_async16(bufb + OFF_A + soA[i], src, ok);
        }
        #pragma unroll
        for (int i = 0; i < 4; i++) {
            int n = lr + i * 32;
            size_t off = (size_t)(colBase + n) * 256 + k0 + lj8;
            cp_async16(bufb + OFF_B + soA[i], B + off, true);
        }
        CP_COMMIT();
    };

    const int bnrow = wn * 32 + ((lane >> 4) & 1) * 8 + (lane & 7);
    const uint32_t bcol16 = (uint32_t)(((lane >> 3) & 1) * 16);
    const int amrow = wm * 64 + (lane & 15);
    const uint32_t acol16 = (uint32_t)((lane >> 4) * 16);

    issue_chunk(0);
    issue_chunk(1);

    for (int c = 0; c < 4; c++) {
        if (c == 3) { CP_WAIT_ALL(); } else { CP_WAIT_1(); }
        __syncthreads();
        if (c + 2 < 4) issue_chunk(c + 2);

        const uint32_t bufb = sb + (uint32_t)(c % 3) * BUF;
        #pragma unroll
        for (int ks = 0; ks < 4; ks++) {
            uint32_t b[4][2];
            uint32_t a[4][4];
            #pragma unroll
            for (int np = 0; np < 2; np++) {
                uint32_t ad = bufb + OFF_B +
                    SW128((uint32_t)((bnrow + np * 16) * 128) + (uint32_t)(ks * 32) + bcol16);
                ldmx4(b[np * 2][0], b[np * 2][1], b[np * 2 + 1][0], b[np * 2 + 1][1], ad);
            }
            #pragma unroll
            for (int mf = 0; mf < 4; mf++) {
                uint32_t ad = bufb + OFF_A +
                    SW128((uint32_t)((amrow + mf * 16) * 128) + (uint32_t)(ks * 32) + acol16);
                ldmx4(a[mf][0], a[mf][1], a[mf][2], a[mf][3], ad);
            }
            #pragma unroll
            for (int mf = 0; mf < 4; mf++)
                #pragma unroll
                for (int nf = 0; nf < 4; nf++)
                    mma16816(&acc[mf * 16 + nf * 4],
                             a[mf][0], a[mf][1], a[mf][2], a[mf][3],
                             b[nf][0], b[nf][1]);
        }
    }

    // ---- epilogue ----
    float* outBase = (z == 1) ? (args.outF + (size_t)args.N * 256) : args.outF;
    const int* inv = (z == 0) ? args.invP : args.invK;
    const int tcolOff = (z == 0) ? 256 : ((z == 1) ? 512 : 0);

    #pragma unroll
    for (int mf = 0; mf < 4; mf++) {
        int r0 = rowBase + wm * 64 + mf * 16 + (lane >> 2);
        #pragma unroll
        for (int half = 0; half < 2; half++) {
            int r = r0 + half * 8;
            if (r >= rowsC) continue;
            int tm = (z == 2) ? r : __ldg(inv + r);
            #pragma unroll
            for (int nf = 0; nf < 4; nf++) {
                int col = colBase + wn * 32 + nf * 8 + (lane & 3) * 2;
                float v0 = acc[mf * 16 + nf * 4 + half * 2 + 0];
                float v1 = acc[mf * 16 + nf * 4 + half * 2 + 1];
                if (tm >= 0) {
                    // row feeds concat; out row gets overwritten by final scatter
                    union { __half h[2]; uint32_t u; } t;
                    t.h[0] = __float2half_rn(tanhf(v0));
                    t.h[1] = __float2half_rn(tanhf(v1));
                    *(uint32_t*)(args.T + (size_t)tm * 768 + tcolOff + col) = t.u;
                } else {
                    *(float2*)(outBase + (size_t)r * 256 + col) = make_float2(v0, v1);
                }
            }
        }
    }
}

// ---------------------------------------------------------------------------
// gemm_final (256 threads, grid.y=2, 2 CTA/SM): BM=128 BN=128 BK=64, K=768,
// 3-stage. +lb, leaky, +bias, scatter to out rows idxP / N+idxK.
// ---------------------------------------------------------------------------
struct ArgsF {
    const __half* Ah;
    const __half* B;
    float* outF;
    const int* idxP;
    const int* idxK;
    const float* lb;
    const float* bias;
    int rowsC;
    int Nfull;
};

__global__ void __launch_bounds__(256, 2)
gemm_final(const ArgsF args)
{
    extern __shared__ char smem[];
    const uint32_t sb = smem_u32(smem);
    const int tid = threadIdx.x;
    const int w = tid >> 5;
    const int lane = tid & 31;
    const int rowBase = blockIdx.x * 128;
    const int colBase = blockIdx.y * 128;
    const int rowsC = args.rowsC;

    const int wm = w & 1;
    const int wn = w >> 1;

    float acc[64];
    #pragma unroll
    for (int i = 0; i < 64; i++) acc[i] = 0.0f;

    const int lr = tid >> 3;
    const int lj8 = (tid & 7) * 8;
    const uint32_t soA[4] = {
        SW128((uint32_t)((lr + 0) * 128 + lj8 * 2)),
        SW128((uint32_t)((lr + 32) * 128 + lj8 * 2)),
        SW128((uint32_t)((lr + 64) * 128 + lj8 * 2)),
        SW128((uint32_t)((lr + 96) * 128 + lj8 * 2))};

    auto issue_chunk = [&](int c) {
        const int k0 = c * 64;
        const uint32_t bufb = sb + (uint32_t)(c % 3) * BUF;
        #pragma unroll
        for (int i = 0; i < 4; i++) {
            int gr = rowBase + lr + i * 32;
            bool ok = (gr < rowsC);
            const __half* src = args.Ah + (size_t)(ok ? gr : 0) * 768 + k0 + lj8;
            cp_async16(bufb + OFF_A + soA[i], src, ok);
        }
        #pragma unroll
        for (int i = 0; i < 4; i++) {
            int n = lr + i * 32;
            size_t off = (size_t)(colBase + n) * 768 + k0 + lj8;
            cp_async16(bufb + OFF_B + soA[i], args.B + off, true);
        }
        CP_COMMIT();
    };

    const int bnrow = wn * 32 + ((lane >> 4) & 1) * 8 + (lane & 7);
    const uint32_t bcol16 = (uint32_t)(((lane >> 3) & 1) * 16);
    const int amrow = wm * 64 + (lane & 15);
    const uint32_t acol16 = (uint32_t)((lane >> 4) * 16);

    issue_chunk(0);
    issue_chunk(1);

    for (int c = 0; c < 12; c++) {
        if (c == 11) { CP_WAIT_ALL(); } else { CP_WAIT_1(); }
        __syncthreads();
        if (c + 2 < 12) issue_chunk(c + 2);

        const uint32_t bufb = sb + (uint32_t)(c % 3) * BUF;
        #pragma unroll
        for (int ks = 0; ks < 4; ks++) {
            uint32_t b[4][2];
            uint32_t a[4][4];
            #pragma unroll
            for (int np = 0; np < 2; np++) {
                uint32_t ad = bufb + OFF_B +
                    SW128((uint32_t)((bnrow + np * 16) * 128) + (uint32_t)(ks * 32) + bcol16);
                ldmx4(b[np * 2][0], b[np * 2][1], b[np * 2 + 1][0], b[np * 2 + 1][1], ad);
            }
            #pragma unroll
            for (int mf = 0; mf < 4; mf++) {
                uint32_t ad = bufb + OFF_A +
                    SW128((uint32_t)((amrow + mf * 16) * 128) + (uint32_t)(ks * 32) + acol16);
                ldmx4(a[mf][0], a[mf][1], a[mf][2], a[mf][3], ad);
            }
            #pragma unroll
            for (int mf = 0; mf < 4; mf++)
                #pragma unroll
                for (int nf = 0; nf < 4; nf++)
                    mma16816(&acc[mf * 16 + nf * 4],
                             a[mf][0], a[mf][1], a[mf][2], a[mf][3],
                             b[nf][0], b[nf][1]);
        }
    }

    #pragma unroll
    for (int mf = 0; mf < 4; mf++) {
        int r0 = rowBase + wm * 64 + mf * 16 + (lane >> 2);
        #pragma unroll
        for (int half = 0; half < 2; half++) {
            int r = r0 + half * 8;
            if (r >= rowsC) continue;
            int pr = __ldg(args.idxP + r);
            int kr = __ldg(args.idxK + r);
            #pragma unroll
            for (int nf = 0; nf < 4; nf++) {
                int col = colBase + wn * 32 + nf * 8 + (lane & 3) * 2;
                float x0 = acc[mf * 16 + nf * 4 + half * 2 + 0] + __ldg(args.lb + col);
                float x1 = acc[mf * 16 + nf * 4 + half * 2 + 1] + __ldg(args.lb + col + 1);
                x0 = (x0 > 0.0f) ? x0 : 0.01f * x0;
                x1 = (x1 > 0.0f) ? x1 : 0.01f * x1;
                x0 += __ldg(args.bias + col);
                x1 += __ldg(args.bias + col + 1);
                float2 v = make_float2(x0, x1);
                *(float2*)(args.outF + (size_t)pr * 256 + col) = v;
                *(float2*)(args.outF + (size_t)(args.Nfull + kr) * 256 + col) = v;
            }
        }
    }
}

// ---------------------------------------------------------------------------
__global__ void init_inv(int* __restrict__ invP, int* __restrict__ invK, int N)
{
    int i = blockIdx.x * blockDim.x + threadIdx.x;
    if (i < N) { invP[i] = -1; invK[i] = -1; }
}

__global__ void prep_all(const float* __restrict__ wo, const float* __restrict__ wp,
                         const float* __restrict__ wk, const float* __restrict__ lw,
                         const float* __restrict__ hp, const float* __restrict__ hk,
                         const float* __restrict__ ho,
                         const int* __restrict__ idxP, const int* __restrict__ idxK,
                         __half* __restrict__ W, __half* __restrict__ L,
                         __half* __restrict__ Ahp, __half* __restrict__ Ahk,
                         __half* __restrict__ Aho,
                         int* __restrict__ invP, int* __restrict__ invK,
                         int N, int M)
{
    int idx = blockIdx.x * blockDim.x + threadIdx.x;
    const int R0 = 3 * 65536;
    const int R1 = R0 + 256 * 768;
    const int R2 = R1 + N * 32;
    const int R3 = R2 + N * 32;
    const int R4 = R3 + M * 32;
    const int R5 = R4 + M;
    const int R6 = R5 + M;
    if (idx < R0) {
        int wi = idx >> 16;
        int e = idx & 65535;
        int k = e >> 8, n = e & 255;
        const float* Wf = (wi == 0) ? wo : ((wi == 1) ? wp : wk);
        W[wi * 65536 + n * 256 + k] = __float2half_rn(Wf[k * 256 + n]);
    } else if (idx < R1) {
        int e = idx - R0;
        L[e] = __float2half_rn(lw[e]);
    } else if (idx < R4) {
        const float* src;
        __half* dst;
        int r, j8;
        if (idx < R2) {
            int e = idx - R1; r = e >> 5; j8 = (e & 31) * 8; src = hp + (size_t)r * 256 + j8; dst = Ahp;
        } else if (idx < R3) {
            int e = idx - R2; r = e >> 5; j8 = (e & 31) * 8; src = hk + (size_t)r * 256 + j8; dst = Ahk;
        } else {
            int e = idx - R3; r = e >> 5; j8 = (e & 31) * 8;
            src = ho + (size_t)__ldg(idxP + r) * 256 + j8; dst = Aho;
        }
        float4 v0 = *(const float4*)src;
        float4 v1 = *(const float4*)(src + 4);
        union { __half h[8]; uint4 u; } t;
        t.h[0] = __float2half_rn(v0.x); t.h[1] = __float2half_rn(v0.y);
        t.h[2] = __float2half_rn(v0.z); t.h[3] = __float2half_rn(v0.w);
        t.h[4] = __float2half_rn(v1.x); t.h[5] = __float2half_rn(v1.y);
        t.h[6] = __float2half_rn(v1.z); t.h[7] = __float2half_rn(v1.w);
        *(uint4*)(dst + (size_t)r * 256 + j8) = t.u;
    } else if (idx < R5) {
        int m = idx - R4;
        invP[__ldg(idxP + m)] = m;
    } else if (idx < R6) {
        int m = idx - R5;
        invK[__ldg(idxK + m)] = m;
    }
}

extern "C" void kernel_launch(void* const* d_in, const int* in_sizes, int n_in,
                              void* d_out, int out_size)
{
    const float* h_p = (const float*)d_in[0];
    const float* h_k = (const float*)d_in[1];
    const float* h_o = (const float*)d_in[2];
    const int* idxP  = (const int*)d_in[3];
    const int* idxK  = (const int*)d_in[4];
    const float* w_o = (const float*)d_in[5];
    const float* w_p = (const float*)d_in[6];
    const float* w_k = (const float*)d_in[7];
    const float* lw  = (const float*)d_in[8];
    const float* lb  = (const float*)d_in[9];
    const float* bs  = (const float*)d_in[10];
    float* out = (float*)d_out;

    const int N = in_sizes[0] / DDIM;
    const int M = in_sizes[3];

    __half *W, *L, *T, *Ahp, *Ahk, *Aho;
    int *invP, *invK;
    cudaGetSymbolAddress((void**)&W, g_W);
    cudaGetSymbolAddress((void**)&L, g_L);
    cudaGetSymbolAddress((void**)&T, g_T);
    cudaGetSymbolAddress((void**)&Ahp, g_Ahp);
    cudaGetSymbolAddress((void**)&Ahk, g_Ahk);
    cudaGetSymbolAddress((void**)&Aho, g_Aho);
    cudaGetSymbolAddress((void**)&invP, g_invP);
    cudaGetSymbolAddress((void**)&invK, g_invK);

    cudaFuncSetAttribute(gemm3, cudaFuncAttributeMaxDynamicSharedMemorySize, SMEM3);
    cudaFuncSetAttribute(gemm_final, cudaFuncAttributeMaxDynamicSharedMemorySize, SMEM3);

    // 1. init inverse maps
    init_inv<<<(N + 255) / 256, 256>>>(invP, invK, N);
    // 2. prep (weights, casts, gather-cast, inverse scatter)
    {
        int total = 3 * 65536 + 256 * 768 + N * 32 + N * 32 + M * 32 + 2 * M;
        prep_all<<<(total + 255) / 256, 256>>>(w_o, w_p, w_k, lw, h_p, h_k, h_o,
                                               idxP, idxK, W, L, Ahp, Ahk, Aho,
                                               invP, invK, N, M);
    }
    // 3. hp/hk/ho GEMMs in one launch; tanh->T fused via inverse maps
    {
        dim3 grd((N + 127) / 128, 2, 3);
        Args3 a = {};
        a.A0 = Ahp; a.A1 = Ahk; a.A2 = Aho;
        a.B0 = W + 1 * 65536; a.B1 = W + 2 * 65536; a.B2 = W + 0 * 65536;
        a.outF = out; a.T = T; a.invP = invP; a.invK = invK;
        a.N = N; a.M = M;
        gemm3<<<grd, 256, SMEM3>>>(a);
    }
    // 4. final linear (K=768) + leaky + bias + scatter
    {
        dim3 grd((M + 127) / 128, 2);
        ArgsF a = {};
        a.Ah = T; a.B = L;
        a.outF = out; a.idxP = idxP; a.idxK = idxK; a.lb = lb; a.bias = bs;
        a.rowsC = M; a.Nfull = N;
        gemm_final<<<grd, 256, SMEM3>>>(a);
    }
}